// round 12
// baseline (speedup 1.0000x reference)
#include <cuda_runtime.h>
#include <cuda_bf16.h>
#include <math.h>
#include <cstdint>

#define BN 8192
#define CN 1000
#define CPAD 1024
#define DN 128
#define NT 64                      // 128-row tiles in B dimension
#define NPAIR (NT * (NT + 1) / 2)  // 2080
#define STRIDE 272                 // bytes per tile row: 256 data + 16 pad
#define TILE_BYTES (128 * STRIDE)  // 34816
#define SMEM_NSD (2 * TILE_BYTES + 512)
#define SMEM_SCL (TILE_BYTES + 4096)

// ---------------- scratch ---------------------------------------------------
__device__ float g_featn[BN * DN];
__device__ __nv_bfloat16 g_featbH[BN * DN];
__device__ __nv_bfloat16 g_featbL[BN * DN];
__device__ float g_meansn[CN * DN];
__device__ __nv_bfloat16 g_meansBH[CPAD * DN];
__device__ __nv_bfloat16 g_meansBL[CPAD * DN];
__device__ float g_XX[BN];
__device__ float g_YY[CN];
__device__ int   g_lab[BN];
__device__ float g_pb[NT * BN];        // 64-slot bottom partials
__device__ float g_S[CN * DN];         // class feature sums
__device__ int   g_cnt[CN];            // class counts
__device__ float g_ce[BN];
__device__ float g_margin[BN];
__device__ float g_peri[BN];
__device__ float g_valid[BN];

__device__ __forceinline__ uint32_t smem_u32(const void* p) {
    uint32_t a;
    asm("{ .reg .u64 t; cvta.to.shared.u64 t, %1; cvt.u32.u64 %0, t; }" : "=r"(a) : "l"(p));
    return a;
}
__device__ __forceinline__ void bf16_split(float x, __nv_bfloat16& hi, __nv_bfloat16& lo) {
    hi = __float2bfloat16(x);
    lo = __float2bfloat16(x - __bfloat162float(hi));
}

#define HMMA4(ACC, A, B0, B1) \
    asm("mma.sync.aligned.m16n8k16.row.col.f32.bf16.bf16.f32 " \
        "{%0,%1,%2,%3}, {%4,%5,%6,%7}, {%8,%9}, {%0,%1,%2,%3};" \
        : "+f"((ACC)[0]), "+f"((ACC)[1]), "+f"((ACC)[2]), "+f"((ACC)[3]) \
        : "r"((A)[0]), "r"((A)[1]), "r"((A)[2]), "r"((A)[3]), "r"(B0), "r"(B1))

#define LDSM4(R, ADDR) \
    asm volatile("ldmatrix.sync.aligned.m8n8.x4.shared.b16 {%0,%1,%2,%3}, [%4];" \
                 : "=r"((R)[0]), "=r"((R)[1]), "=r"((R)[2]), "=r"((R)[3]) : "r"(ADDR))

// ---------------- prep -------------------------------------------------------
__global__ void prep_feat_kernel(const float* __restrict__ feat,
                                 const int* __restrict__ labels) {
    int row = blockIdx.x * 8 + threadIdx.y;
    int lane = threadIdx.x;
    float4 v = ((const float4*)(feat + (size_t)row * DN))[lane];
    float ss = v.x * v.x + v.y * v.y + v.z * v.z + v.w * v.w;
    #pragma unroll
    for (int d = 16; d; d >>= 1) ss += __shfl_xor_sync(0xffffffffu, ss, d);
    float inv = 1.0f / fmaxf(sqrtf(ss), 1e-12f);
    float4 o = make_float4(v.x * inv, v.y * inv, v.z * inv, v.w * inv);
    ((float4*)(g_featn + (size_t)row * DN))[lane] = o;

    __nv_bfloat16 hx, lx, hy, ly, hz, lz, hw, lw;
    bf16_split(o.x, hx, lx); bf16_split(o.y, hy, ly);
    bf16_split(o.z, hz, lz); bf16_split(o.w, hw, lw);
    __nv_bfloat162 h0 = __nv_bfloat162(hx, hy), h1 = __nv_bfloat162(hz, hw);
    __nv_bfloat162 l0 = __nv_bfloat162(lx, ly), l1 = __nv_bfloat162(lz, lw);
    ((uint2*)(g_featbH + (size_t)row * DN))[lane] = make_uint2(*(uint32_t*)&h0, *(uint32_t*)&h1);
    ((uint2*)(g_featbL + (size_t)row * DN))[lane] = make_uint2(*(uint32_t*)&l0, *(uint32_t*)&l1);
    if (lane == 0) {
        g_XX[row] = ss * inv * inv;
        g_lab[row] = labels[row];
    }
}

__global__ void prep_means_kernel(const float* __restrict__ means) {
    int row = blockIdx.x * 8 + threadIdx.y;
    int lane = threadIdx.x;
    float4 v = make_float4(0.f, 0.f, 0.f, 0.f);
    if (row < CN) v = ((const float4*)(means + (size_t)row * DN))[lane];
    float ss = v.x * v.x + v.y * v.y + v.z * v.z + v.w * v.w;
    #pragma unroll
    for (int d = 16; d; d >>= 1) ss += __shfl_xor_sync(0xffffffffu, ss, d);
    float inv = 1.0f / fmaxf(sqrtf(ss), 1e-12f);

    __nv_bfloat16 hx, lx, hy, ly, hz, lz, hw, lw;
    bf16_split(v.x, hx, lx); bf16_split(v.y, hy, ly);
    bf16_split(v.z, hz, lz); bf16_split(v.w, hw, lw);
    __nv_bfloat162 h0 = __nv_bfloat162(hx, hy), h1 = __nv_bfloat162(hz, hw);
    __nv_bfloat162 l0 = __nv_bfloat162(lx, ly), l1 = __nv_bfloat162(lz, lw);
    ((uint2*)(g_meansBH + (size_t)row * DN))[lane] = make_uint2(*(uint32_t*)&h0, *(uint32_t*)&h1);
    ((uint2*)(g_meansBL + (size_t)row * DN))[lane] = make_uint2(*(uint32_t*)&l0, *(uint32_t*)&l1);

    if (row < CN) {
        float4 o = make_float4(v.x * inv, v.y * inv, v.z * inv, v.w * inv);
        ((float4*)(g_meansn + (size_t)row * DN))[lane] = o;
        if (lane == 0) g_YY[row] = ss;
    }
}

// ---------------- class sums: one warp per class (deterministic) -------------
__global__ void __launch_bounds__(256) class_sum_kernel() {
    int w = threadIdx.x >> 5, l = threadIdx.x & 31;
    int c = blockIdx.x * 8 + w;
    float4 acc = make_float4(0.f, 0.f, 0.f, 0.f);
    int count = 0;
    for (int base = 0; base < BN; base += 32) {
        int lb = g_lab[base + l];
        unsigned m = __ballot_sync(0xffffffffu, lb == c);
        count += __popc(m);
        while (m) {
            int j = __ffs(m) - 1;
            m &= m - 1;
            float4 f = ((const float4*)(g_featn + (size_t)(base + j) * DN))[l];
            acc.x += f.x; acc.y += f.y; acc.z += f.z; acc.w += f.w;
        }
    }
    ((float4*)(g_S + (size_t)c * DN))[l] = acc;
    if (l == 0) g_cnt[c] = count;
}

// copy a 128-row bf16 tile into padded smem; each thread: one half-row (128 B)
__device__ __forceinline__ void load_tile(char* dst, const __nv_bfloat16* src_base,
                                          int row0, int tid) {
    int r = tid >> 1, h = tid & 1;
    const uint4* src = (const uint4*)(src_base + (size_t)(row0 + r) * DN + h * 64);
    uint4* d = (uint4*)(dst + r * STRIDE + h * 128);
    #pragma unroll
    for (int i = 0; i < 8; i++) d[i] = src[i];
}

__device__ __forceinline__ void load_a_frags16(uint32_t base, int row0, int l, uint32_t a[8][4]) {
    uint32_t row = row0 + (l & 15);
    uint32_t koff = 8 * (l >> 4);
    #pragma unroll
    for (int ks = 0; ks < 8; ks++) {
        uint32_t addr = base + row * STRIDE + (16 * ks + koff) * 2;
        LDSM4(a[ks], addr);
    }
}

// ---------------- nsd GEMM via split-bf16 mma.sync (unchanged R11) -----------
__global__ void __launch_bounds__(256) nsd_mma_kernel(float* __restrict__ out) {
    extern __shared__ __align__(16) char sm[];
    char* smX = sm;
    char* smY = sm + TILE_BYTES;
    float* smYY = (float*)(sm + 2 * TILE_BYTES);

    int tid = threadIdx.x;
    int w = tid >> 5, l = tid & 31;
    int ib = blockIdx.x * 128;
    int cb = blockIdx.y * 128;

    load_tile(smX, g_featbH, ib, tid);
    load_tile(smY, g_featbL, ib, tid);
    __syncthreads();

    uint32_t ah[8][4], al[8][4];
    load_a_frags16(smem_u32(smX), 16 * w, l, ah);
    load_a_frags16(smem_u32(smY), 16 * w, l, al);
    __syncthreads();

    load_tile(smX, g_meansBH, cb, tid);
    load_tile(smY, g_meansBL, cb, tid);
    if (tid < 128) {
        int c = cb + tid;
        smYY[tid] = (c < CN) ? (-0.5f * g_YY[c]) : 0.f;
    }
    __syncthreads();

    int r0 = 16 * w + (l >> 2), r1 = r0 + 8;
    int i0 = ib + r0, i1 = ib + r1;
    float nx0 = -0.5f * g_XX[i0], nx1 = -0.5f * g_XX[i1];

    uint32_t baseH = smem_u32(smX), baseL = smem_u32(smY);
    uint32_t brow = (l & 7);
    uint32_t bkoff = 8 * (l >> 3);

    #pragma unroll
    for (int nb = 0; nb < 16; nb++) {
        float hh[4] = {0.f, 0.f, 0.f, 0.f};
        float lh[4] = {0.f, 0.f, 0.f, 0.f};
        float hl[4] = {0.f, 0.f, 0.f, 0.f};
        #pragma unroll
        for (int kp = 0; kp < 4; kp++) {
            uint32_t off = (nb * 8 + brow) * STRIDE + (32 * kp + bkoff) * 2;
            uint32_t bh[4], bl[4];
            LDSM4(bh, baseH + off);
            LDSM4(bl, baseL + off);
            HMMA4(hh, ah[2 * kp],     bh[0], bh[1]);
            HMMA4(lh, al[2 * kp],     bh[0], bh[1]);
            HMMA4(hl, ah[2 * kp],     bl[0], bl[1]);
            HMMA4(hh, ah[2 * kp + 1], bh[2], bh[3]);
            HMMA4(lh, al[2 * kp + 1], bh[2], bh[3]);
            HMMA4(hl, ah[2 * kp + 1], bl[2], bl[3]);
        }
        int colloc = nb * 8 + 2 * (l & 3);
        int col = cb + colloc;
        float y0 = smYY[colloc], y1 = smYY[colloc + 1];
        if (col < CN) {
            out[(size_t)i0 * CN + col] = nx0 + (hh[0] + lh[0] + hl[0]) + y0;
            out[(size_t)i1 * CN + col] = nx1 + (hh[2] + lh[2] + hl[2]) + y0;
        }
        if (col + 1 < CN) {
            out[(size_t)i0 * CN + col + 1] = nx0 + (hh[1] + lh[1] + hl[1]) + y1;
            out[(size_t)i1 * CN + col + 1] = nx1 + (hh[3] + lh[3] + hl[3]) + y1;
        }
    }
}

// ---------------- CE + margin (unchanged) ------------------------------------
__global__ void __launch_bounds__(256) ce_kernel(const float* __restrict__ nsd) {
    int w = threadIdx.x >> 5, l = threadIdx.x & 31;
    int i = blockIdx.x * 8 + w;
    int lab = g_lab[i];
    const float4* row = (const float4*)(nsd + (size_t)i * CN);

    float4 v[8];
    float m = -1e30f, vlab = -1e30f;
    #pragma unroll
    for (int k = 0; k < 8; k++) {
        int idx = l + 32 * k;
        float4 x = make_float4(-1e30f, -1e30f, -1e30f, -1e30f);
        if (idx < 250) {
            x = row[idx];
            int c0 = idx * 4;
            if (lab == c0)     { x.x *= 1.5f; vlab = x.x; }
            if (lab == c0 + 1) { x.y *= 1.5f; vlab = x.y; }
            if (lab == c0 + 2) { x.z *= 1.5f; vlab = x.z; }
            if (lab == c0 + 3) { x.w *= 1.5f; vlab = x.w; }
            m = fmaxf(m, fmaxf(fmaxf(x.x, x.y), fmaxf(x.z, x.w)));
        }
        v[k] = x;
    }
    #pragma unroll
    for (int d = 16; d; d >>= 1) {
        m = fmaxf(m, __shfl_xor_sync(0xffffffffu, m, d));
        vlab = fmaxf(vlab, __shfl_xor_sync(0xffffffffu, vlab, d));
    }
    float e = 0.f;
    #pragma unroll
    for (int k = 0; k < 8; k++)
        e += __expf(v[k].x - m) + __expf(v[k].y - m)
           + __expf(v[k].z - m) + __expf(v[k].w - m);
    #pragma unroll
    for (int d = 16; d; d >>= 1) e += __shfl_xor_sync(0xffffffffu, e, d);
    if (l == 0) g_ce[i] = -(vlab - m - logf(e));

    float4 f  = ((const float4*)(g_featn  + (size_t)i   * DN))[l];
    float4 mm = ((const float4*)(g_meansn + (size_t)lab * DN))[l];
    float dx = f.x - mm.x, dy = f.y - mm.y, dz = f.z - mm.z, dw = f.w - mm.w;
    float ms = dx * dx + dy * dy + dz * dz + dw * dw;
    #pragma unroll
    for (int d = 16; d; d >>= 1) ms += __shfl_xor_sync(0xffffffffu, ms, d);
    if (l == 0) g_margin[i] = ms;
}

// ---------------- SCL symmetric: upper-triangular tile pairs -----------------
// CTA = pair (I,J), I<=J, 128x128 tile. 8 warps: strip=(w&3)*32 rows, half=(w>>2) of nb.
// Row bottoms -> slot J; col bottoms -> slot I. 64 slots cover each row exactly once.
__global__ void __launch_bounds__(256, 2) scl_sym_kernel() {
    extern __shared__ __align__(16) char sm[];
    char* smT = sm;
    float* rowB = (float*)(sm + TILE_BYTES);          // [2][128]
    float* colB = (float*)(sm + TILE_BYTES + 1024);   // [4][128]

    int tid = threadIdx.x;
    int w = tid >> 5;
    int l = tid & 31;
    int strip = w & 3;
    int half = w >> 2;

    // decode pair (I, J)
    int b = blockIdx.x;
    int I = (int)((129.0f - sqrtf(16641.0f - 8.0f * (float)b)) * 0.5f);
    while ((I + 1) * (129 - (I + 1)) / 2 <= b) I++;
    while (I * (129 - I) / 2 > b) I--;
    int J = I + (b - I * (129 - I) / 2);
    int Ibase = I * 128, Jbase = J * 128;

    // stage tile I, extract A fragments (32 rows per warp)
    load_tile(smT, g_featbH, Ibase, tid);
    __syncthreads();
    uint32_t a[2][8][4];
    {
        uint32_t base = smem_u32(smT);
        load_a_frags16(base, strip * 32,      l, a[0]);
        load_a_frags16(base, strip * 32 + 16, l, a[1]);
    }
    __syncthreads();
    if (J != I) {
        load_tile(smT, g_featbH, Jbase, tid);
        __syncthreads();
    }

    const float invT = 1.0f / 0.3f;
    int rl0 = strip * 32 + (l >> 2);            // local row of first accum row
    int ig0 = Ibase + rl0;
    float sB[4] = {0.f, 0.f, 0.f, 0.f};

    uint32_t bbase = smem_u32(smT);
    uint32_t brow = (l & 7);
    uint32_t bkoff = 8 * (l >> 3);
    bool diag = (J == I);

    #pragma unroll
    for (int nb = 0; nb < 8; nb++) {
        int nbg = half * 8 + nb;
        float e0[4] = {0.f, 0.f, 0.f, 0.f}, o0[4] = {0.f, 0.f, 0.f, 0.f};
        float e1[4] = {0.f, 0.f, 0.f, 0.f}, o1[4] = {0.f, 0.f, 0.f, 0.f};
        #pragma unroll
        for (int kp = 0; kp < 4; kp++) {
            uint32_t bq[4];
            LDSM4(bq, bbase + (nbg * 8 + brow) * STRIDE + (32 * kp + bkoff) * 2);
            HMMA4(e0, a[0][2 * kp],     bq[0], bq[1]);
            HMMA4(e1, a[1][2 * kp],     bq[0], bq[1]);
            HMMA4(o0, a[0][2 * kp + 1], bq[2], bq[3]);
            HMMA4(o1, a[1][2 * kp + 1], bq[2], bq[3]);
        }
        int col = nbg * 8 + 2 * (l & 3);
        int jg0 = Jbase + col, jg1 = jg0 + 1;

        // exp of sims (bottom contributions)
        float x00 = __expf((e0[0] + o0[0]) * invT);
        float x01 = __expf((e0[1] + o0[1]) * invT);
        float x10 = __expf((e0[2] + o0[2]) * invT);
        float x11 = __expf((e0[3] + o0[3]) * invT);
        float x20 = __expf((e1[0] + o1[0]) * invT);
        float x21 = __expf((e1[1] + o1[1]) * invT);
        float x30 = __expf((e1[2] + o1[2]) * invT);
        float x31 = __expf((e1[3] + o1[3]) * invT);

        if (diag) {
            // mask self-pairs; row contributions only (full square present)
            if (jg0 == ig0)      x00 = 0.f;
            if (jg1 == ig0)      x01 = 0.f;
            if (jg0 == ig0 + 8)  x10 = 0.f;
            if (jg1 == ig0 + 8)  x11 = 0.f;
            if (jg0 == ig0 + 16) x20 = 0.f;
            if (jg1 == ig0 + 16) x21 = 0.f;
            if (jg0 == ig0 + 24) x30 = 0.f;
            if (jg1 == ig0 + 24) x31 = 0.f;
        }
        sB[0] += x00 + x01;
        sB[1] += x10 + x11;
        sB[2] += x20 + x21;
        sB[3] += x30 + x31;

        if (!diag) {
            // column sums across the warp's 32 rows, then across 8 lane-groups
            float vc0 = x00 + x10 + x20 + x30;
            float vc1 = x01 + x11 + x21 + x31;
            #pragma unroll
            for (int d = 4; d <= 16; d <<= 1) {
                vc0 += __shfl_down_sync(0xffffffffu, vc0, d);
                vc1 += __shfl_down_sync(0xffffffffu, vc1, d);
            }
            if (l < 4) {
                int c = nbg * 8 + 2 * l;
                colB[strip * 128 + c]     = vc0;
                colB[strip * 128 + c + 1] = vc1;
            }
        }
    }

    // row partial reduce (width-4) and stage to smem
    #pragma unroll
    for (int q = 0; q < 4; q++) {
        #pragma unroll
        for (int d = 2; d; d >>= 1) sB[q] += __shfl_down_sync(0xffffffffu, sB[q], d, 4);
    }
    if ((l & 3) == 0) {
        #pragma unroll
        for (int q = 0; q < 4; q++) rowB[half * 128 + rl0 + 8 * q] = sB[q];
    }
    __syncthreads();

    if (tid < 128) {
        g_pb[(size_t)J * BN + Ibase + tid] = rowB[tid] + rowB[128 + tid];
    } else if (!diag) {
        int c = tid - 128;
        g_pb[(size_t)I * BN + Jbase + c] =
            colB[c] + colB[128 + c] + colB[256 + c] + colB[384 + c];
    }
}

// ---------------- combine: bottom + closed-form positives --------------------
__global__ void combine_kernel() {
    int i = blockIdx.x * 256 + threadIdx.x;
    float bsum = 0.f;
    #pragma unroll 8
    for (int s = 0; s < NT; s++) bsum += g_pb[(size_t)s * BN + i];

    int lab = g_lab[i];
    int cnt = g_cnt[lab] - 1;

    const float* fi = g_featn + (size_t)i * DN;
    const float* sc = g_S + (size_t)lab * DN;
    float dotS = 0.f, dotSelf = 0.f;
    #pragma unroll 8
    for (int k = 0; k < DN / 4; k++) {
        float4 f = ((const float4*)fi)[k];
        float4 s4 = ((const float4*)sc)[k];
        dotS += f.x * s4.x + f.y * s4.y + f.z * s4.z + f.w * s4.w;
        dotSelf += f.x * f.x + f.y * f.y + f.z * f.z + f.w * f.w;
    }
    const float invT = 1.0f / 0.3f;
    float pp = (dotS - dotSelf) * invT;

    bool valid = (cnt > 0);
    g_peri[i]  = valid ? (pp / (float)cnt - logf(bsum)) : 0.f;
    g_valid[i] = valid ? 1.f : 0.f;
}

__global__ void final_kernel(float* __restrict__ out, long long scalar_idx) {
    int t = threadIdx.x;
    float sp = 0.f, sv = 0.f, sc = 0.f, smg = 0.f;
    for (int i = t; i < BN; i += 256) {
        sp += g_peri[i];
        sv += g_valid[i];
        sc += g_ce[i];
        smg += g_margin[i];
    }
    __shared__ float r0[256], r1[256], r2[256], r3[256];
    r0[t] = sp; r1[t] = sv; r2[t] = sc; r3[t] = smg;
    __syncthreads();
    for (int d = 128; d; d >>= 1) {
        if (t < d) { r0[t] += r0[t+d]; r1[t] += r1[t+d]; r2[t] += r2[t+d]; r3[t] += r3[t+d]; }
        __syncthreads();
    }
    if (t == 0) {
        float scl = -r0[0] / fmaxf(r1[0], 1.f);
        float ce  = r2[0] / (float)BN;
        float lm  = r3[0] / (2.f * (float)BN);
        out[scalar_idx] = 0.9f * ce + 0.1f * scl + 0.5f * lm;
    }
}

// ---------------- launch ------------------------------------------------------
extern "C" void kernel_launch(void* const* d_in, const int* in_sizes, int n_in,
                              void* d_out, int out_size) {
    const float* feat   = (const float*)d_in[0];
    const int*   labels = (const int*)d_in[1];
    const float* means  = (const float*)d_in[2];
    float* out = (float*)d_out;

    static cudaStream_t sB = nullptr;
    static cudaEvent_t  eF = nullptr, eJ = nullptr;
    static int initTried = 0;
    if (!initTried) {
        initTried = 1;
        if (cudaStreamCreateWithFlags(&sB, cudaStreamNonBlocking) != cudaSuccess) sB = nullptr;
        if (sB) {
            if (cudaEventCreateWithFlags(&eF, cudaEventDisableTiming) != cudaSuccess) { eF = nullptr; }
            if (cudaEventCreateWithFlags(&eJ, cudaEventDisableTiming) != cudaSuccess) { eJ = nullptr; }
            if (!eF || !eJ) sB = nullptr;
        }
        cudaFuncSetAttribute(nsd_mma_kernel, cudaFuncAttributeMaxDynamicSharedMemorySize, SMEM_NSD);
        cudaFuncSetAttribute(scl_sym_kernel, cudaFuncAttributeMaxDynamicSharedMemorySize, SMEM_SCL);
    }
    bool fork = (sB != nullptr);

    prep_feat_kernel<<<BN / 8, dim3(32, 8)>>>(feat, labels);

    if (fork) {
        cudaEventRecord(eF, 0);
        cudaStreamWaitEvent(sB, eF, 0);
        scl_sym_kernel<<<NPAIR, 256, SMEM_SCL, sB>>>();
        cudaEventRecord(eJ, sB);
    }

    prep_means_kernel<<<CPAD / 8, dim3(32, 8)>>>(means);
    nsd_mma_kernel<<<dim3(BN / 128, CPAD / 128), 256, SMEM_NSD>>>(out);
    ce_kernel<<<BN / 8, 256>>>(out);
    class_sum_kernel<<<CN / 8, 256>>>();

    if (fork) {
        cudaStreamWaitEvent(0, eJ, 0);
    } else {
        scl_sym_kernel<<<NPAIR, 256, SMEM_SCL>>>();
    }

    combine_kernel<<<BN / 256, 256>>>();
    final_kernel<<<1, 256>>>(out, (long long)out_size - 1);
}

// round 13
// speedup vs baseline: 1.0070x; 1.0070x over previous
#include <cuda_runtime.h>
#include <cuda_bf16.h>
#include <math.h>
#include <cstdint>

#define BN 8192
#define CN 1000
#define CPAD 1024
#define DN 128
#define TSPLIT 8
#define STRIDE 272                 // bytes per tile row: 256 data + 16 pad (conflict-free ldmatrix)
#define TILE_BYTES (128 * STRIDE)  // 34816
#define SMEM_NSD (2 * TILE_BYTES + 512)
#define SMEM_SCL (TILE_BYTES + 512)

// ---------------- scratch ---------------------------------------------------
__device__ float g_featn[BN * DN];
__device__ __nv_bfloat16 g_featbH[BN * DN];
__device__ __nv_bfloat16 g_featbL[BN * DN];
__device__ float g_meansn[CN * DN];
__device__ __nv_bfloat16 g_meansBH[CPAD * DN];
__device__ __nv_bfloat16 g_meansBL[CPAD * DN];
__device__ float g_XX[BN];
__device__ float g_YY[CN];
__device__ int   g_lab[BN];
__device__ float g_pb[TSPLIT * BN];    // bottom partials
__device__ float g_S[CN * DN];         // class feature sums
__device__ int   g_cnt[CN];            // class counts
__device__ float g_ce[BN];
__device__ float g_margin[BN];
__device__ float g_peri[BN];
__device__ float g_valid[BN];

__device__ __forceinline__ uint32_t smem_u32(const void* p) {
    uint32_t a;
    asm("{ .reg .u64 t; cvta.to.shared.u64 t, %1; cvt.u32.u64 %0, t; }" : "=r"(a) : "l"(p));
    return a;
}
__device__ __forceinline__ void bf16_split(float x, __nv_bfloat16& hi, __nv_bfloat16& lo) {
    hi = __float2bfloat16(x);
    lo = __float2bfloat16(x - __bfloat162float(hi));
}

#define HMMA4(ACC, A, B0, B1) \
    asm("mma.sync.aligned.m16n8k16.row.col.f32.bf16.bf16.f32 " \
        "{%0,%1,%2,%3}, {%4,%5,%6,%7}, {%8,%9}, {%0,%1,%2,%3};" \
        : "+f"((ACC)[0]), "+f"((ACC)[1]), "+f"((ACC)[2]), "+f"((ACC)[3]) \
        : "r"((A)[0]), "r"((A)[1]), "r"((A)[2]), "r"((A)[3]), "r"(B0), "r"(B1))

#define LDSM4(R, ADDR) \
    asm volatile("ldmatrix.sync.aligned.m8n8.x4.shared.b16 {%0,%1,%2,%3}, [%4];" \
                 : "=r"((R)[0]), "=r"((R)[1]), "=r"((R)[2]), "=r"((R)[3]) : "r"(ADDR))

// ---------------- prep -------------------------------------------------------
__global__ void prep_feat_kernel(const float* __restrict__ feat,
                                 const int* __restrict__ labels) {
    int row = blockIdx.x * 8 + threadIdx.y;
    int lane = threadIdx.x;
    float4 v = ((const float4*)(feat + (size_t)row * DN))[lane];
    float ss = v.x * v.x + v.y * v.y + v.z * v.z + v.w * v.w;
    #pragma unroll
    for (int d = 16; d; d >>= 1) ss += __shfl_xor_sync(0xffffffffu, ss, d);
    float inv = 1.0f / fmaxf(sqrtf(ss), 1e-12f);
    float4 o = make_float4(v.x * inv, v.y * inv, v.z * inv, v.w * inv);
    ((float4*)(g_featn + (size_t)row * DN))[lane] = o;

    __nv_bfloat16 hx, lx, hy, ly, hz, lz, hw, lw;
    bf16_split(o.x, hx, lx); bf16_split(o.y, hy, ly);
    bf16_split(o.z, hz, lz); bf16_split(o.w, hw, lw);
    __nv_bfloat162 h0 = __nv_bfloat162(hx, hy), h1 = __nv_bfloat162(hz, hw);
    __nv_bfloat162 l0 = __nv_bfloat162(lx, ly), l1 = __nv_bfloat162(lz, lw);
    ((uint2*)(g_featbH + (size_t)row * DN))[lane] = make_uint2(*(uint32_t*)&h0, *(uint32_t*)&h1);
    ((uint2*)(g_featbL + (size_t)row * DN))[lane] = make_uint2(*(uint32_t*)&l0, *(uint32_t*)&l1);
    if (lane == 0) {
        g_XX[row] = ss * inv * inv;
        g_lab[row] = labels[row];
    }
}

__global__ void prep_means_kernel(const float* __restrict__ means) {
    int row = blockIdx.x * 8 + threadIdx.y;
    int lane = threadIdx.x;
    float4 v = make_float4(0.f, 0.f, 0.f, 0.f);
    if (row < CN) v = ((const float4*)(means + (size_t)row * DN))[lane];
    float ss = v.x * v.x + v.y * v.y + v.z * v.z + v.w * v.w;
    #pragma unroll
    for (int d = 16; d; d >>= 1) ss += __shfl_xor_sync(0xffffffffu, ss, d);
    float inv = 1.0f / fmaxf(sqrtf(ss), 1e-12f);

    __nv_bfloat16 hx, lx, hy, ly, hz, lz, hw, lw;
    bf16_split(v.x, hx, lx); bf16_split(v.y, hy, ly);
    bf16_split(v.z, hz, lz); bf16_split(v.w, hw, lw);
    __nv_bfloat162 h0 = __nv_bfloat162(hx, hy), h1 = __nv_bfloat162(hz, hw);
    __nv_bfloat162 l0 = __nv_bfloat162(lx, ly), l1 = __nv_bfloat162(lz, lw);
    ((uint2*)(g_meansBH + (size_t)row * DN))[lane] = make_uint2(*(uint32_t*)&h0, *(uint32_t*)&h1);
    ((uint2*)(g_meansBL + (size_t)row * DN))[lane] = make_uint2(*(uint32_t*)&l0, *(uint32_t*)&l1);

    if (row < CN) {
        float4 o = make_float4(v.x * inv, v.y * inv, v.z * inv, v.w * inv);
        ((float4*)(g_meansn + (size_t)row * DN))[lane] = o;
        if (lane == 0) g_YY[row] = ss;
    }
}

// ---------------- class sums: one warp per class (deterministic) -------------
__global__ void __launch_bounds__(256) class_sum_kernel() {
    int w = threadIdx.x >> 5, l = threadIdx.x & 31;
    int c = blockIdx.x * 8 + w;
    float4 acc = make_float4(0.f, 0.f, 0.f, 0.f);
    int count = 0;
    for (int base = 0; base < BN; base += 32) {
        int lb = g_lab[base + l];
        unsigned m = __ballot_sync(0xffffffffu, lb == c);
        count += __popc(m);
        while (m) {
            int j = __ffs(m) - 1;
            m &= m - 1;
            float4 f = ((const float4*)(g_featn + (size_t)(base + j) * DN))[l];
            acc.x += f.x; acc.y += f.y; acc.z += f.z; acc.w += f.w;
        }
    }
    ((float4*)(g_S + (size_t)c * DN))[l] = acc;
    if (l == 0) g_cnt[c] = count;
}

// copy a 128-row bf16 tile into padded smem; each thread: one half-row (128 B)
__device__ __forceinline__ void load_tile(char* dst, const __nv_bfloat16* src_base,
                                          int row0, int tid) {
    int r = tid >> 1, h = tid & 1;
    const uint4* src = (const uint4*)(src_base + (size_t)(row0 + r) * DN + h * 64);
    uint4* d = (uint4*)(dst + r * STRIDE + h * 128);
    #pragma unroll
    for (int i = 0; i < 8; i++) d[i] = src[i];
}

__device__ __forceinline__ void load_a_frags16(uint32_t base, int row0, int l, uint32_t a[8][4]) {
    uint32_t row = row0 + (l & 15);
    uint32_t koff = 8 * (l >> 4);
    #pragma unroll
    for (int ks = 0; ks < 8; ks++) {
        uint32_t addr = base + row * STRIDE + (16 * ks + koff) * 2;
        LDSM4(a[ks], addr);
    }
}

// ---------------- nsd GEMM via split-bf16 mma.sync ---------------------------
__global__ void __launch_bounds__(256) nsd_mma_kernel(float* __restrict__ out) {
    extern __shared__ __align__(16) char sm[];
    char* smX = sm;
    char* smY = sm + TILE_BYTES;
    float* smYY = (float*)(sm + 2 * TILE_BYTES);

    int tid = threadIdx.x;
    int w = tid >> 5, l = tid & 31;
    int ib = blockIdx.x * 128;
    int cb = blockIdx.y * 128;

    load_tile(smX, g_featbH, ib, tid);
    load_tile(smY, g_featbL, ib, tid);
    __syncthreads();

    uint32_t ah[8][4], al[8][4];
    load_a_frags16(smem_u32(smX), 16 * w, l, ah);
    load_a_frags16(smem_u32(smY), 16 * w, l, al);
    __syncthreads();

    load_tile(smX, g_meansBH, cb, tid);
    load_tile(smY, g_meansBL, cb, tid);
    if (tid < 128) {
        int c = cb + tid;
        smYY[tid] = (c < CN) ? (-0.5f * g_YY[c]) : 0.f;
    }
    __syncthreads();

    int r0 = 16 * w + (l >> 2), r1 = r0 + 8;
    int i0 = ib + r0, i1 = ib + r1;
    float nx0 = -0.5f * g_XX[i0], nx1 = -0.5f * g_XX[i1];

    uint32_t baseH = smem_u32(smX), baseL = smem_u32(smY);
    uint32_t brow = (l & 7);
    uint32_t bkoff = 8 * (l >> 3);

    #pragma unroll
    for (int nb = 0; nb < 16; nb++) {
        float hh[4] = {0.f, 0.f, 0.f, 0.f};
        float lh[4] = {0.f, 0.f, 0.f, 0.f};
        float hl[4] = {0.f, 0.f, 0.f, 0.f};
        #pragma unroll
        for (int kp = 0; kp < 4; kp++) {
            uint32_t off = (nb * 8 + brow) * STRIDE + (32 * kp + bkoff) * 2;
            uint32_t bh[4], bl[4];
            LDSM4(bh, baseH + off);
            LDSM4(bl, baseL + off);
            HMMA4(hh, ah[2 * kp],     bh[0], bh[1]);
            HMMA4(lh, al[2 * kp],     bh[0], bh[1]);
            HMMA4(hl, ah[2 * kp],     bl[0], bl[1]);
            HMMA4(hh, ah[2 * kp + 1], bh[2], bh[3]);
            HMMA4(lh, al[2 * kp + 1], bh[2], bh[3]);
            HMMA4(hl, ah[2 * kp + 1], bl[2], bl[3]);
        }
        int colloc = nb * 8 + 2 * (l & 3);
        int col = cb + colloc;
        float y0 = smYY[colloc], y1 = smYY[colloc + 1];
        if (col < CN) {
            out[(size_t)i0 * CN + col] = nx0 + (hh[0] + lh[0] + hl[0]) + y0;
            out[(size_t)i1 * CN + col] = nx1 + (hh[2] + lh[2] + hl[2]) + y0;
        }
        if (col + 1 < CN) {
            out[(size_t)i0 * CN + col + 1] = nx0 + (hh[1] + lh[1] + hl[1]) + y1;
            out[(size_t)i1 * CN + col + 1] = nx1 + (hh[3] + lh[3] + hl[3]) + y1;
        }
    }
}

// ---------------- CE + margin ------------------------------------------------
__global__ void __launch_bounds__(256) ce_kernel(const float* __restrict__ nsd) {
    int w = threadIdx.x >> 5, l = threadIdx.x & 31;
    int i = blockIdx.x * 8 + w;
    int lab = g_lab[i];
    const float4* row = (const float4*)(nsd + (size_t)i * CN);

    float4 v[8];
    float m = -1e30f, vlab = -1e30f;
    #pragma unroll
    for (int k = 0; k < 8; k++) {
        int idx = l + 32 * k;
        float4 x = make_float4(-1e30f, -1e30f, -1e30f, -1e30f);
        if (idx < 250) {
            x = row[idx];
            int c0 = idx * 4;
            if (lab == c0)     { x.x *= 1.5f; vlab = x.x; }
            if (lab == c0 + 1) { x.y *= 1.5f; vlab = x.y; }
            if (lab == c0 + 2) { x.z *= 1.5f; vlab = x.z; }
            if (lab == c0 + 3) { x.w *= 1.5f; vlab = x.w; }
            m = fmaxf(m, fmaxf(fmaxf(x.x, x.y), fmaxf(x.z, x.w)));
        }
        v[k] = x;
    }
    #pragma unroll
    for (int d = 16; d; d >>= 1) {
        m = fmaxf(m, __shfl_xor_sync(0xffffffffu, m, d));
        vlab = fmaxf(vlab, __shfl_xor_sync(0xffffffffu, vlab, d));
    }
    float e = 0.f;
    #pragma unroll
    for (int k = 0; k < 8; k++)
        e += __expf(v[k].x - m) + __expf(v[k].y - m)
           + __expf(v[k].z - m) + __expf(v[k].w - m);
    #pragma unroll
    for (int d = 16; d; d >>= 1) e += __shfl_xor_sync(0xffffffffu, e, d);
    if (l == 0) g_ce[i] = -(vlab - m - logf(e));

    float4 f  = ((const float4*)(g_featn  + (size_t)i   * DN))[l];
    float4 mm = ((const float4*)(g_meansn + (size_t)lab * DN))[l];
    float dx = f.x - mm.x, dy = f.y - mm.y, dz = f.z - mm.z, dw = f.w - mm.w;
    float ms = dx * dx + dy * dy + dz * dz + dw * dw;
    #pragma unroll
    for (int d = 16; d; d >>= 1) ms += __shfl_xor_sync(0xffffffffu, ms, d);
    if (l == 0) g_margin[i] = ms;
}

// ---------------- SCL: bottom-only fused GEMM + row reduction ----------------
// CTA = 256 i-rows x 128 j-cols; 8 warps x 32 rows -> 4 HMMA per B LDSM.x4
__global__ void __launch_bounds__(256, 2) scl_mma_kernel() {
    extern __shared__ __align__(16) char sm[];
    char* smT = sm;

    int tid = threadIdx.x;
    int w = tid >> 5;
    int l = tid & 31;
    int ib = blockIdx.x * 256;
    int split = blockIdx.y;

    uint32_t a[2][8][4];   // [strip 0/1][k-step][frag]

    // half 0 (rows ib..ib+127): warps 0-3 extract their 2 strips
    load_tile(smT, g_featbH, ib, tid);
    __syncthreads();
    if (w < 4) {
        uint32_t base = smem_u32(smT);
        load_a_frags16(base, 32 * w,      l, a[0]);
        load_a_frags16(base, 32 * w + 16, l, a[1]);
    }
    __syncthreads();
    // half 1 (rows ib+128..ib+255): warps 4-7 extract
    load_tile(smT, g_featbH, ib + 128, tid);
    __syncthreads();
    if (w >= 4) {
        uint32_t base = smem_u32(smT);
        load_a_frags16(base, 32 * (w - 4),      l, a[0]);
        load_a_frags16(base, 32 * (w - 4) + 16, l, a[1]);
    }

    // this thread's 4 output rows (global)
    int ig[4];
    {
        int base_r = ib + 32 * w + (l >> 2);
        ig[0] = base_r;      ig[1] = base_r + 8;
        ig[2] = base_r + 16; ig[3] = base_r + 24;
    }

    const float invT = 1.0f / 0.3f;
    float sB[4] = {0.f, 0.f, 0.f, 0.f};

    uint32_t bbase = smem_u32(smT);
    uint32_t brow = (l & 7);
    uint32_t bkoff = 8 * (l >> 3);

    for (int jt = 0; jt < 64 / TSPLIT; jt++) {
        int jb = (split * (64 / TSPLIT) + jt) * 128;

        __syncthreads();   // previous tile (or A extraction) fully consumed
        load_tile(smT, g_featbH, jb, tid);
        __syncthreads();

        #pragma unroll
        for (int nb = 0; nb < 16; nb++) {
            float e0[4] = {0.f, 0.f, 0.f, 0.f}, o0[4] = {0.f, 0.f, 0.f, 0.f};
            float e1[4] = {0.f, 0.f, 0.f, 0.f}, o1[4] = {0.f, 0.f, 0.f, 0.f};
            #pragma unroll
            for (int kp = 0; kp < 4; kp++) {
                uint32_t b[4];
                LDSM4(b, bbase + (nb * 8 + brow) * STRIDE + (32 * kp + bkoff) * 2);
                HMMA4(e0, a[0][2 * kp],     b[0], b[1]);
                HMMA4(e1, a[1][2 * kp],     b[0], b[1]);
                HMMA4(o0, a[0][2 * kp + 1], b[2], b[3]);
                HMMA4(o1, a[1][2 * kp + 1], b[2], b[3]);
            }
            int col = nb * 8 + 2 * (l & 3);
            int jg0 = jb + col, jg1 = jg0 + 1;

            float s0 = (e0[0] + o0[0]) * invT;
            float s1 = (e0[1] + o0[1]) * invT;
            float s2 = (e0[2] + o0[2]) * invT;
            float s3 = (e0[3] + o0[3]) * invT;
            float s4 = (e1[0] + o1[0]) * invT;
            float s5 = (e1[1] + o1[1]) * invT;
            float s6 = (e1[2] + o1[2]) * invT;
            float s7 = (e1[3] + o1[3]) * invT;

            if (jg0 != ig[0]) sB[0] += __expf(s0);
            if (jg1 != ig[0]) sB[0] += __expf(s1);
            if (jg0 != ig[1]) sB[1] += __expf(s2);
            if (jg1 != ig[1]) sB[1] += __expf(s3);
            if (jg0 != ig[2]) sB[2] += __expf(s4);
            if (jg1 != ig[2]) sB[2] += __expf(s5);
            if (jg0 != ig[3]) sB[3] += __expf(s6);
            if (jg1 != ig[3]) sB[3] += __expf(s7);
        }
    }

    // deterministic reduce across the 4 lanes sharing each row
    #pragma unroll
    for (int q = 0; q < 4; q++) {
        #pragma unroll
        for (int d = 2; d; d >>= 1)
            sB[q] += __shfl_down_sync(0xffffffffu, sB[q], d, 4);
    }
    if ((l & 3) == 0) {
        #pragma unroll
        for (int q = 0; q < 4; q++)
            g_pb[split * BN + ig[q]] = sB[q];
    }
}

// ---------------- combine: bottom + closed-form positives --------------------
__global__ void combine_kernel() {
    int i = blockIdx.x * 256 + threadIdx.x;
    float bsum = 0.f;
    #pragma unroll
    for (int s = 0; s < TSPLIT; s++) bsum += g_pb[s * BN + i];

    int lab = g_lab[i];
    int cnt = g_cnt[lab] - 1;

    const float* fi = g_featn + (size_t)i * DN;
    const float* sc = g_S + (size_t)lab * DN;
    float dotS = 0.f, dotSelf = 0.f;
    #pragma unroll 8
    for (int k = 0; k < DN / 4; k++) {
        float4 f = ((const float4*)fi)[k];
        float4 s4 = ((const float4*)sc)[k];
        dotS += f.x * s4.x + f.y * s4.y + f.z * s4.z + f.w * s4.w;
        dotSelf += f.x * f.x + f.y * f.y + f.z * f.z + f.w * f.w;
    }
    const float invT = 1.0f / 0.3f;
    float pp = (dotS - dotSelf) * invT;

    bool valid = (cnt > 0);
    g_peri[i]  = valid ? (pp / (float)cnt - logf(bsum)) : 0.f;
    g_valid[i] = valid ? 1.f : 0.f;
}

__global__ void final_kernel(float* __restrict__ out, long long scalar_idx) {
    int t = threadIdx.x;
    float sp = 0.f, sv = 0.f, sc = 0.f, smg = 0.f;
    for (int i = t; i < BN; i += 256) {
        sp += g_peri[i];
        sv += g_valid[i];
        sc += g_ce[i];
        smg += g_margin[i];
    }
    __shared__ float r0[256], r1[256], r2[256], r3[256];
    r0[t] = sp; r1[t] = sv; r2[t] = sc; r3[t] = smg;
    __syncthreads();
    for (int d = 128; d; d >>= 1) {
        if (t < d) { r0[t] += r0[t+d]; r1[t] += r1[t+d]; r2[t] += r2[t+d]; r3[t] += r3[t+d]; }
        __syncthreads();
    }
    if (t == 0) {
        float scl = -r0[0] / fmaxf(r1[0], 1.f);
        float ce  = r2[0] / (float)BN;
        float lm  = r3[0] / (2.f * (float)BN);
        out[scalar_idx] = 0.9f * ce + 0.1f * scl + 0.5f * lm;
    }
}

// ---------------- launch ------------------------------------------------------
extern "C" void kernel_launch(void* const* d_in, const int* in_sizes, int n_in,
                              void* d_out, int out_size) {
    const float* feat   = (const float*)d_in[0];
    const int*   labels = (const int*)d_in[1];
    const float* means  = (const float*)d_in[2];
    float* out = (float*)d_out;

    static cudaStream_t sB = nullptr;
    static cudaEvent_t  eF = nullptr, eJ = nullptr;
    static int initTried = 0;
    if (!initTried) {
        initTried = 1;
        if (cudaStreamCreateWithFlags(&sB, cudaStreamNonBlocking) != cudaSuccess) sB = nullptr;
        if (sB) {
            if (cudaEventCreateWithFlags(&eF, cudaEventDisableTiming) != cudaSuccess) { eF = nullptr; }
            if (cudaEventCreateWithFlags(&eJ, cudaEventDisableTiming) != cudaSuccess) { eJ = nullptr; }
            if (!eF || !eJ) sB = nullptr;
        }
        cudaFuncSetAttribute(nsd_mma_kernel, cudaFuncAttributeMaxDynamicSharedMemorySize, SMEM_NSD);
        cudaFuncSetAttribute(scl_mma_kernel, cudaFuncAttributeMaxDynamicSharedMemorySize, SMEM_SCL);
    }
    bool fork = (sB != nullptr);

    prep_feat_kernel<<<BN / 8, dim3(32, 8)>>>(feat, labels);

    if (fork) {
        cudaEventRecord(eF, 0);
        cudaStreamWaitEvent(sB, eF, 0);
        scl_mma_kernel<<<dim3(BN / 256, TSPLIT), 256, SMEM_SCL, sB>>>();
        cudaEventRecord(eJ, sB);
    }

    prep_means_kernel<<<CPAD / 8, dim3(32, 8)>>>(means);
    nsd_mma_kernel<<<dim3(BN / 128, CPAD / 128), 256, SMEM_NSD>>>(out);
    ce_kernel<<<BN / 8, 256>>>(out);
    class_sum_kernel<<<CN / 8, 256>>>();

    if (fork) {
        cudaStreamWaitEvent(0, eJ, 0);
    } else {
        scl_mma_kernel<<<dim3(BN / 256, TSPLIT), 256, SMEM_SCL>>>();
    }

    combine_kernel<<<BN / 256, 256>>>();
    final_kernel<<<1, 256>>>(out, (long long)out_size - 1);
}

// round 14
// speedup vs baseline: 2.1267x; 2.1118x over previous
#include <cuda_runtime.h>
#include <cuda_bf16.h>
#include <math.h>
#include <cstdint>

#define BN 8192
#define CN 1000
#define CPAD 1024
#define DN 128
#define TSPLIT 8
#define STRIDE 272                 // bytes per tile row: 256 data + 16 pad (conflict-free ldmatrix)
#define TILE_BYTES (128 * STRIDE)  // 34816
#define SMEM_NSD (2 * TILE_BYTES + 512)
#define SMEM_SCL (TILE_BYTES + 512)

// ---------------- scratch ---------------------------------------------------
__device__ float g_featn[BN * DN];
__device__ __nv_bfloat16 g_featbH[BN * DN];
__device__ __nv_bfloat16 g_featbL[BN * DN];
__device__ float g_meansn[CN * DN];
__device__ __nv_bfloat16 g_meansBH[CPAD * DN];
__device__ __nv_bfloat16 g_meansBL[CPAD * DN];
__device__ float g_XX[BN];
__device__ float g_YY[CN];
__device__ int   g_lab[BN];
__device__ float g_pb[TSPLIT * BN];
__device__ float g_pp[TSPLIT * BN];
__device__ int   g_pc[TSPLIT * BN];
__device__ float g_ce[BN];
__device__ float g_margin[BN];
__device__ float g_peri[BN];
__device__ float g_valid[BN];

__device__ __forceinline__ uint32_t smem_u32(const void* p) {
    uint32_t a;
    asm("{ .reg .u64 t; cvta.to.shared.u64 t, %1; cvt.u32.u64 %0, t; }" : "=r"(a) : "l"(p));
    return a;
}
__device__ __forceinline__ void bf16_split(float x, __nv_bfloat16& hi, __nv_bfloat16& lo) {
    hi = __float2bfloat16(x);
    lo = __float2bfloat16(x - __bfloat162float(hi));
}

#define HMMA4(ACC, A, B0, B1) \
    asm("mma.sync.aligned.m16n8k16.row.col.f32.bf16.bf16.f32 " \
        "{%0,%1,%2,%3}, {%4,%5,%6,%7}, {%8,%9}, {%0,%1,%2,%3};" \
        : "+f"((ACC)[0]), "+f"((ACC)[1]), "+f"((ACC)[2]), "+f"((ACC)[3]) \
        : "r"((A)[0]), "r"((A)[1]), "r"((A)[2]), "r"((A)[3]), "r"(B0), "r"(B1))

#define LDSM4(R, ADDR) \
    asm volatile("ldmatrix.sync.aligned.m8n8.x4.shared.b16 {%0,%1,%2,%3}, [%4];" \
                 : "=r"((R)[0]), "=r"((R)[1]), "=r"((R)[2]), "=r"((R)[3]) : "r"(ADDR))

// ---------------- prep -------------------------------------------------------
__global__ void prep_feat_kernel(const float* __restrict__ feat,
                                 const int* __restrict__ labels) {
    int row = blockIdx.x * 8 + threadIdx.y;
    int lane = threadIdx.x;
    float4 v = ((const float4*)(feat + (size_t)row * DN))[lane];
    float ss = v.x * v.x + v.y * v.y + v.z * v.z + v.w * v.w;
    #pragma unroll
    for (int d = 16; d; d >>= 1) ss += __shfl_xor_sync(0xffffffffu, ss, d);
    float inv = 1.0f / fmaxf(sqrtf(ss), 1e-12f);
    float4 o = make_float4(v.x * inv, v.y * inv, v.z * inv, v.w * inv);
    ((float4*)(g_featn + (size_t)row * DN))[lane] = o;

    __nv_bfloat16 hx, lx, hy, ly, hz, lz, hw, lw;
    bf16_split(o.x, hx, lx); bf16_split(o.y, hy, ly);
    bf16_split(o.z, hz, lz); bf16_split(o.w, hw, lw);
    __nv_bfloat162 h0 = __nv_bfloat162(hx, hy), h1 = __nv_bfloat162(hz, hw);
    __nv_bfloat162 l0 = __nv_bfloat162(lx, ly), l1 = __nv_bfloat162(lz, lw);
    ((uint2*)(g_featbH + (size_t)row * DN))[lane] = make_uint2(*(uint32_t*)&h0, *(uint32_t*)&h1);
    ((uint2*)(g_featbL + (size_t)row * DN))[lane] = make_uint2(*(uint32_t*)&l0, *(uint32_t*)&l1);
    if (lane == 0) {
        g_XX[row] = ss * inv * inv;
        g_lab[row] = labels[row];
    }
}

__global__ void prep_means_kernel(const float* __restrict__ means) {
    int row = blockIdx.x * 8 + threadIdx.y;   // 128 blocks * 8 = 1024 (padded)
    int lane = threadIdx.x;
    float4 v = make_float4(0.f, 0.f, 0.f, 0.f);
    if (row < CN) v = ((const float4*)(means + (size_t)row * DN))[lane];
    float ss = v.x * v.x + v.y * v.y + v.z * v.z + v.w * v.w;
    #pragma unroll
    for (int d = 16; d; d >>= 1) ss += __shfl_xor_sync(0xffffffffu, ss, d);
    float inv = 1.0f / fmaxf(sqrtf(ss), 1e-12f);

    __nv_bfloat16 hx, lx, hy, ly, hz, lz, hw, lw;
    bf16_split(v.x, hx, lx); bf16_split(v.y, hy, ly);
    bf16_split(v.z, hz, lz); bf16_split(v.w, hw, lw);
    __nv_bfloat162 h0 = __nv_bfloat162(hx, hy), h1 = __nv_bfloat162(hz, hw);
    __nv_bfloat162 l0 = __nv_bfloat162(lx, ly), l1 = __nv_bfloat162(lz, lw);
    ((uint2*)(g_meansBH + (size_t)row * DN))[lane] = make_uint2(*(uint32_t*)&h0, *(uint32_t*)&h1);
    ((uint2*)(g_meansBL + (size_t)row * DN))[lane] = make_uint2(*(uint32_t*)&l0, *(uint32_t*)&l1);

    if (row < CN) {
        float4 o = make_float4(v.x * inv, v.y * inv, v.z * inv, v.w * inv);
        ((float4*)(g_meansn + (size_t)row * DN))[lane] = o;
        if (lane == 0) g_YY[row] = ss;
    }
}

// copy a 128-row bf16 tile into padded smem; each thread: one half-row (128 B)
__device__ __forceinline__ void load_tile(char* dst, const __nv_bfloat16* src_base,
                                          int row0, int tid) {
    int r = tid >> 1, h = tid & 1;
    const uint4* src = (const uint4*)(src_base + (size_t)(row0 + r) * DN + h * 64);
    uint4* d = (uint4*)(dst + r * STRIDE + h * 128);
    #pragma unroll
    for (int i = 0; i < 8; i++) d[i] = src[i];
}

// extract a warp's 16-row A fragments (8 k-steps) starting at tile row `row0`
__device__ __forceinline__ void load_a_frags16(uint32_t base, int row0, int l, uint32_t a[8][4]) {
    uint32_t row = row0 + (l & 15);
    uint32_t koff = 8 * (l >> 4);
    #pragma unroll
    for (int ks = 0; ks < 8; ks++) {
        uint32_t addr = base + row * STRIDE + (16 * ks + koff) * 2;
        LDSM4(a[ks], addr);
    }
}

// ---------------- nsd GEMM via split-bf16 mma.sync ---------------------------
// XY = Ah*Bh + Ah*Bl + Al*Bh (fp32 accum, 3 independent chains); out = -0.5*XX + XY - 0.5*YY
__global__ void __launch_bounds__(256) nsd_mma_kernel(float* __restrict__ out) {
    extern __shared__ __align__(16) char sm[];
    char* smX = sm;
    char* smY = sm + TILE_BYTES;
    float* smYY = (float*)(sm + 2 * TILE_BYTES);

    int tid = threadIdx.x;
    int w = tid >> 5, l = tid & 31;
    int ib = blockIdx.x * 128;
    int cb = blockIdx.y * 128;

    load_tile(smX, g_featbH, ib, tid);
    load_tile(smY, g_featbL, ib, tid);
    __syncthreads();

    uint32_t ah[8][4], al[8][4];
    load_a_frags16(smem_u32(smX), 16 * w, l, ah);
    load_a_frags16(smem_u32(smY), 16 * w, l, al);
    __syncthreads();

    load_tile(smX, g_meansBH, cb, tid);
    load_tile(smY, g_meansBL, cb, tid);
    if (tid < 128) {
        int c = cb + tid;
        smYY[tid] = (c < CN) ? (-0.5f * g_YY[c]) : 0.f;
    }
    __syncthreads();

    int r0 = 16 * w + (l >> 2), r1 = r0 + 8;
    int i0 = ib + r0, i1 = ib + r1;
    float nx0 = -0.5f * g_XX[i0], nx1 = -0.5f * g_XX[i1];

    uint32_t baseH = smem_u32(smX), baseL = smem_u32(smY);
    uint32_t brow = (l & 7);
    uint32_t bkoff = 8 * (l >> 3);

    #pragma unroll
    for (int nb = 0; nb < 16; nb++) {
        float hh[4] = {0.f, 0.f, 0.f, 0.f};
        float lh[4] = {0.f, 0.f, 0.f, 0.f};
        float hl[4] = {0.f, 0.f, 0.f, 0.f};
        #pragma unroll
        for (int kp = 0; kp < 4; kp++) {
            uint32_t off = (nb * 8 + brow) * STRIDE + (32 * kp + bkoff) * 2;
            uint32_t bh[4], bl[4];
            LDSM4(bh, baseH + off);
            LDSM4(bl, baseL + off);
            HMMA4(hh, ah[2 * kp],     bh[0], bh[1]);
            HMMA4(lh, al[2 * kp],     bh[0], bh[1]);
            HMMA4(hl, ah[2 * kp],     bl[0], bl[1]);
            HMMA4(hh, ah[2 * kp + 1], bh[2], bh[3]);
            HMMA4(lh, al[2 * kp + 1], bh[2], bh[3]);
            HMMA4(hl, ah[2 * kp + 1], bl[2], bl[3]);
        }
        int colloc = nb * 8 + 2 * (l & 3);
        int col = cb + colloc;
        float y0 = smYY[colloc], y1 = smYY[colloc + 1];
        if (col < CN) {
            out[(size_t)i0 * CN + col] = nx0 + (hh[0] + lh[0] + hl[0]) + y0;
            out[(size_t)i1 * CN + col] = nx1 + (hh[2] + lh[2] + hl[2]) + y0;
        }
        if (col + 1 < CN) {
            out[(size_t)i0 * CN + col + 1] = nx0 + (hh[1] + lh[1] + hl[1]) + y1;
            out[(size_t)i1 * CN + col + 1] = nx1 + (hh[3] + lh[3] + hl[3]) + y1;
        }
    }
}

// ---------------- CE + margin: one warp per row ------------------------------
__global__ void __launch_bounds__(256) ce_kernel(const float* __restrict__ nsd) {
    int w = threadIdx.x >> 5, l = threadIdx.x & 31;
    int i = blockIdx.x * 8 + w;
    int lab = g_lab[i];
    const float4* row = (const float4*)(nsd + (size_t)i * CN);

    float4 v[8];
    float m = -1e30f, vlab = -1e30f;
    #pragma unroll
    for (int k = 0; k < 8; k++) {
        int idx = l + 32 * k;
        float4 x = make_float4(-1e30f, -1e30f, -1e30f, -1e30f);
        if (idx < 250) {
            x = row[idx];
            int c0 = idx * 4;
            if (lab == c0)     { x.x *= 1.5f; vlab = x.x; }
            if (lab == c0 + 1) { x.y *= 1.5f; vlab = x.y; }
            if (lab == c0 + 2) { x.z *= 1.5f; vlab = x.z; }
            if (lab == c0 + 3) { x.w *= 1.5f; vlab = x.w; }
            m = fmaxf(m, fmaxf(fmaxf(x.x, x.y), fmaxf(x.z, x.w)));
        }
        v[k] = x;
    }
    #pragma unroll
    for (int d = 16; d; d >>= 1) {
        m = fmaxf(m, __shfl_xor_sync(0xffffffffu, m, d));
        vlab = fmaxf(vlab, __shfl_xor_sync(0xffffffffu, vlab, d));
    }
    float e = 0.f;
    #pragma unroll
    for (int k = 0; k < 8; k++)
        e += __expf(v[k].x - m) + __expf(v[k].y - m)
           + __expf(v[k].z - m) + __expf(v[k].w - m);
    #pragma unroll
    for (int d = 16; d; d >>= 1) e += __shfl_xor_sync(0xffffffffu, e, d);
    if (l == 0) g_ce[i] = -(vlab - m - logf(e));

    float4 f  = ((const float4*)(g_featn  + (size_t)i   * DN))[l];
    float4 mm = ((const float4*)(g_meansn + (size_t)lab * DN))[l];
    float dx = f.x - mm.x, dy = f.y - mm.y, dz = f.z - mm.z, dw = f.w - mm.w;
    float ms = dx * dx + dy * dy + dz * dz + dw * dw;
    #pragma unroll
    for (int d = 16; d; d >>= 1) ms += __shfl_xor_sync(0xffffffffu, ms, d);
    if (l == 0) g_margin[i] = ms;
}

// ---------------- SCL: mma.sync bf16 fused GEMM + row reduction --------------
// CTA = 256 i-rows x 128 j-cols; 8 warps x 32 rows -> 4 HMMA per B LDSM.x4
__global__ void __launch_bounds__(256, 2) scl_mma_kernel() {
    extern __shared__ __align__(16) char sm[];
    char* smT = sm;
    int* jl = (int*)(sm + TILE_BYTES);

    int tid = threadIdx.x;
    int w = tid >> 5;
    int l = tid & 31;
    int ib = blockIdx.x * 256;
    int split = blockIdx.y;

    uint32_t a[2][8][4];   // [strip 0/1][k-step][frag]

    // half 0 (rows ib..ib+127): warps 0-3 extract their 2 strips
    load_tile(smT, g_featbH, ib, tid);
    __syncthreads();
    if (w < 4) {
        uint32_t base = smem_u32(smT);
        load_a_frags16(base, 32 * w,      l, a[0]);
        load_a_frags16(base, 32 * w + 16, l, a[1]);
    }
    __syncthreads();
    // half 1 (rows ib+128..ib+255): warps 4-7 extract
    load_tile(smT, g_featbH, ib + 128, tid);
    __syncthreads();
    if (w >= 4) {
        uint32_t base = smem_u32(smT);
        load_a_frags16(base, 32 * (w - 4),      l, a[0]);
        load_a_frags16(base, 32 * (w - 4) + 16, l, a[1]);
    }
    // loop-top __syncthreads() covers extraction before B overwrites

    // this thread's 4 output rows (global)
    int ig[4], lab[4];
    {
        int base_r = ib + 32 * w + (l >> 2);
        ig[0] = base_r;      ig[1] = base_r + 8;
        ig[2] = base_r + 16; ig[3] = base_r + 24;
        #pragma unroll
        for (int q = 0; q < 4; q++) lab[q] = g_lab[ig[q]];
    }

    const float invT = 1.0f / 0.3f;
    float sB[4] = {0.f, 0.f, 0.f, 0.f};
    float sP[4] = {0.f, 0.f, 0.f, 0.f};
    int   sC[4] = {0, 0, 0, 0};

    uint32_t bbase = smem_u32(smT);
    uint32_t brow = (l & 7);
    uint32_t bkoff = 8 * (l >> 3);

    for (int jt = 0; jt < 64 / TSPLIT; jt++) {
        int jb = (split * (64 / TSPLIT) + jt) * 128;

        __syncthreads();   // previous tile (or A extraction) fully consumed
        load_tile(smT, g_featbH, jb, tid);
        if (tid < 128) jl[tid] = g_lab[jb + tid];
        __syncthreads();

        #pragma unroll
        for (int nb = 0; nb < 16; nb++) {
            // 4 independent chains: strip0/strip1 x even/odd k
            float e0[4] = {0.f, 0.f, 0.f, 0.f}, o0[4] = {0.f, 0.f, 0.f, 0.f};
            float e1[4] = {0.f, 0.f, 0.f, 0.f}, o1[4] = {0.f, 0.f, 0.f, 0.f};
            #pragma unroll
            for (int kp = 0; kp < 4; kp++) {
                uint32_t b[4];
                LDSM4(b, bbase + (nb * 8 + brow) * STRIDE + (32 * kp + bkoff) * 2);
                HMMA4(e0, a[0][2 * kp],     b[0], b[1]);
                HMMA4(e1, a[1][2 * kp],     b[0], b[1]);
                HMMA4(o0, a[0][2 * kp + 1], b[2], b[3]);
                HMMA4(o1, a[1][2 * kp + 1], b[2], b[3]);
            }
            int col = nb * 8 + 2 * (l & 3);
            int jg0 = jb + col, jg1 = jg0 + 1;
            int jl0 = jl[col], jl1 = jl[col + 1];

            float s0 = (e0[0] + o0[0]) * invT;   // (ig0, jg0)
            float s1 = (e0[1] + o0[1]) * invT;   // (ig0, jg1)
            float s2 = (e0[2] + o0[2]) * invT;   // (ig1, jg0)
            float s3 = (e0[3] + o0[3]) * invT;   // (ig1, jg1)
            float s4 = (e1[0] + o1[0]) * invT;   // (ig2, jg0)
            float s5 = (e1[1] + o1[1]) * invT;   // (ig2, jg1)
            float s6 = (e1[2] + o1[2]) * invT;   // (ig3, jg0)
            float s7 = (e1[3] + o1[3]) * invT;   // (ig3, jg1)

            if (jg0 != ig[0]) { sB[0] += __expf(s0); if (jl0 == lab[0]) { sP[0] += s0; sC[0]++; } }
            if (jg1 != ig[0]) { sB[0] += __expf(s1); if (jl1 == lab[0]) { sP[0] += s1; sC[0]++; } }
            if (jg0 != ig[1]) { sB[1] += __expf(s2); if (jl0 == lab[1]) { sP[1] += s2; sC[1]++; } }
            if (jg1 != ig[1]) { sB[1] += __expf(s3); if (jl1 == lab[1]) { sP[1] += s3; sC[1]++; } }
            if (jg0 != ig[2]) { sB[2] += __expf(s4); if (jl0 == lab[2]) { sP[2] += s4; sC[2]++; } }
            if (jg1 != ig[2]) { sB[2] += __expf(s5); if (jl1 == lab[2]) { sP[2] += s5; sC[2]++; } }
            if (jg0 != ig[3]) { sB[3] += __expf(s6); if (jl0 == lab[3]) { sP[3] += s6; sC[3]++; } }
            if (jg1 != ig[3]) { sB[3] += __expf(s7); if (jl1 == lab[3]) { sP[3] += s7; sC[3]++; } }
        }
    }

    // deterministic reduce across the 4 lanes sharing each row (width-4 segments)
    #pragma unroll
    for (int q = 0; q < 4; q++) {
        #pragma unroll
        for (int d = 2; d; d >>= 1) {
            sB[q] += __shfl_down_sync(0xffffffffu, sB[q], d, 4);
            sP[q] += __shfl_down_sync(0xffffffffu, sP[q], d, 4);
            sC[q] += __shfl_down_sync(0xffffffffu, sC[q], d, 4);
        }
    }
    if ((l & 3) == 0) {
        #pragma unroll
        for (int q = 0; q < 4; q++) {
            g_pb[split * BN + ig[q]] = sB[q];
            g_pp[split * BN + ig[q]] = sP[q];
            g_pc[split * BN + ig[q]] = sC[q];
        }
    }
}

// ---------------- combine + final --------------------------------------------
__global__ void combine_kernel() {
    int i = blockIdx.x * 256 + threadIdx.x;
    float b = 0.f, p = 0.f;
    int c = 0;
    #pragma unroll
    for (int s = 0; s < TSPLIT; s++) {
        b += g_pb[s * BN + i];
        p += g_pp[s * BN + i];
        c += g_pc[s * BN + i];
    }
    bool valid = (c > 0);
    g_peri[i]  = valid ? (p / (float)c - logf(b)) : 0.f;
    g_valid[i] = valid ? 1.f : 0.f;
}

__global__ void final_kernel(float* __restrict__ out, long long scalar_idx) {
    int t = threadIdx.x;
    float sp = 0.f, sv = 0.f, sc = 0.f, smg = 0.f;
    for (int i = t; i < BN; i += 256) {
        sp += g_peri[i];
        sv += g_valid[i];
        sc += g_ce[i];
        smg += g_margin[i];
    }
    __shared__ float r0[256], r1[256], r2[256], r3[256];
    r0[t] = sp; r1[t] = sv; r2[t] = sc; r3[t] = smg;
    __syncthreads();
    for (int d = 128; d; d >>= 1) {
        if (t < d) { r0[t] += r0[t+d]; r1[t] += r1[t+d]; r2[t] += r2[t+d]; r3[t] += r3[t+d]; }
        __syncthreads();
    }
    if (t == 0) {
        float scl = -r0[0] / fmaxf(r1[0], 1.f);
        float ce  = r2[0] / (float)BN;
        float lm  = r3[0] / (2.f * (float)BN);
        out[scalar_idx] = 0.9f * ce + 0.1f * scl + 0.5f * lm;
    }
}

// ---------------- launch ------------------------------------------------------
extern "C" void kernel_launch(void* const* d_in, const int* in_sizes, int n_in,
                              void* d_out, int out_size) {
    const float* feat   = (const float*)d_in[0];
    const int*   labels = (const int*)d_in[1];
    const float* means  = (const float*)d_in[2];
    float* out = (float*)d_out;

    static cudaStream_t sB = nullptr;
    static cudaEvent_t  eF = nullptr, eJ = nullptr;
    static int initTried = 0;
    if (!initTried) {
        initTried = 1;
        if (cudaStreamCreateWithFlags(&sB, cudaStreamNonBlocking) != cudaSuccess) sB = nullptr;
        if (sB) {
            if (cudaEventCreateWithFlags(&eF, cudaEventDisableTiming) != cudaSuccess) { eF = nullptr; }
            if (cudaEventCreateWithFlags(&eJ, cudaEventDisableTiming) != cudaSuccess) { eJ = nullptr; }
            if (!eF || !eJ) sB = nullptr;
        }
        cudaFuncSetAttribute(nsd_mma_kernel, cudaFuncAttributeMaxDynamicSharedMemorySize, SMEM_NSD);
        cudaFuncSetAttribute(scl_mma_kernel, cudaFuncAttributeMaxDynamicSharedMemorySize, SMEM_SCL);
    }
    bool fork = (sB != nullptr);

    prep_feat_kernel<<<BN / 8, dim3(32, 8)>>>(feat, labels);

    if (fork) {
        cudaEventRecord(eF, 0);
        cudaStreamWaitEvent(sB, eF, 0);
        scl_mma_kernel<<<dim3(BN / 256, TSPLIT), 256, SMEM_SCL, sB>>>();
        cudaEventRecord(eJ, sB);
    }

    prep_means_kernel<<<CPAD / 8, dim3(32, 8)>>>(means);
    nsd_mma_kernel<<<dim3(BN / 128, CPAD / 128), 256, SMEM_NSD>>>(out);
    ce_kernel<<<BN / 8, 256>>>(out);

    if (fork) {
        cudaStreamWaitEvent(0, eJ, 0);
    } else {
        scl_mma_kernel<<<dim3(BN / 256, TSPLIT), 256, SMEM_SCL>>>();
    }

    combine_kernel<<<BN / 256, 256>>>();
    final_kernel<<<1, 256>>>(out, (long long)out_size - 1);
}